// round 2
// baseline (speedup 1.0000x reference)
#include <cuda_runtime.h>
#include <cstdint>

#define N_NODES 100000
#define N_EDGES 1600000
#define NF 100
#define NH 32

// ---------------- device scratch (no allocations allowed) ----------------
__device__ int   g_is64;
__device__ int   g_deg [N_NODES];
__device__ float g_dinv[N_NODES];
__device__ float g_h   [N_NODES * NH];   // h = x @ W1
__device__ float g_out1[N_NODES * NH];   // aggregated layer-1 (pre-bias)
__device__ float g_g   [N_NODES * 2];    // g = dropout(relu(out1+b1)) @ W2

// ---------------- helpers ----------------
__device__ __forceinline__ int ld_idx(const void* ei, long long pos, int is64) {
    if (is64) return (int)((const long long*)ei)[pos];
    return ((const int*)ei)[pos];
}

__device__ __forceinline__ void red_add_v4(float* p, float4 v) {
    asm volatile("red.global.add.v4.f32 [%0], {%1,%2,%3,%4};"
                 :: "l"(p), "f"(v.x), "f"(v.y), "f"(v.z), "f"(v.w) : "memory");
}
__device__ __forceinline__ void red_add_v2(float* p, float a, float b) {
    asm volatile("red.global.add.v2.f32 [%0], {%1,%2};"
                 :: "l"(p), "f"(a), "f"(b) : "memory");
}

// JAX threefry2x32, key = (0, 42)  [jax.random.key(42)], 20 rounds
__device__ __forceinline__ uint2 threefry_0_42(unsigned x0, unsigned x1) {
    const unsigned ks0 = 0u, ks1 = 42u, ks2 = 0x1BD11BDAu ^ 42u;
    x0 += ks0; x1 += ks1;
#define TFR(r) { x0 += x1; x1 = ((x1 << (r)) | (x1 >> (32 - (r)))) ^ x0; }
    TFR(13) TFR(15) TFR(26) TFR(6)
    x0 += ks1; x1 += ks2 + 1u;
    TFR(17) TFR(29) TFR(16) TFR(24)
    x0 += ks2; x1 += ks0 + 2u;
    TFR(13) TFR(15) TFR(26) TFR(6)
    x0 += ks0; x1 += ks1 + 3u;
    TFR(17) TFR(29) TFR(16) TFR(24)
    x0 += ks1; x1 += ks2 + 4u;
    TFR(13) TFR(15) TFR(26) TFR(6)
    x0 += ks2; x1 += ks0 + 5u;
#undef TFR
    return make_uint2(x0, x1);
}

// Partitionable-threefry 32-bit random bits for flat element index idx:
// counter = (hi=0, lo=idx), bits = out0 ^ out1.
__device__ __forceinline__ unsigned rng_bits_partitionable(unsigned idx) {
    uint2 o = threefry_0_42(0u, idx);
    return o.x ^ o.y;
}

// ---------------- kernels ----------------

// Detect int64 vs int32 edge_index: int64 node ids < 2^31 -> all odd 32-bit
// words (high halves) are zero. int32 -> odd words are random node ids.
__global__ void k_detect(const unsigned* ei) {
    __shared__ int s_any;
    if (threadIdx.x == 0) s_any = 0;
    __syncthreads();
    int any = 0;
    for (int i = threadIdx.x; i < 1024; i += blockDim.x)
        if (ei[2 * i + 1] != 0u) any = 1;
    if (any) atomicOr(&s_any, 1);
    __syncthreads();
    if (threadIdx.x == 0) g_is64 = s_any ? 0 : 1;
}

__global__ void k_deg_init() {
    int i = blockIdx.x * blockDim.x + threadIdx.x;
    if (i < N_NODES) g_deg[i] = 1;  // self loop
}

__global__ void k_deg_count(const void* ei) {
    int e = blockIdx.x * blockDim.x + threadIdx.x;
    if (e >= N_EDGES) return;
    int is64 = g_is64;
    int d = ld_idx(ei, (long long)N_EDGES + e, is64);
    atomicAdd(&g_deg[d], 1);
}

__global__ void k_dinv() {
    int i = blockIdx.x * blockDim.x + threadIdx.x;
    if (i < N_NODES) g_dinv[i] = rsqrtf((float)g_deg[i]);
}

// h = x @ W1 ; also write out1 = h * dinv^2 (self-loop contribution).
// Block: 256 threads, 128 rows x 32 cols. Thread: 4 rows x 4 cols.
__global__ __launch_bounds__(256) void k_gemm1(const float* __restrict__ x,
                                               const float* __restrict__ W1) {
    __shared__ float Ws[NF * NH];      // 100x32
    __shared__ float xs[20 * 132];     // k-chunk of x, transposed, padded stride
    const int tid  = threadIdx.x;
    const int row0 = blockIdx.x * 128;
    const int rg = tid >> 3;           // 0..31 -> rows rg*4..rg*4+3
    const int cg = tid & 7;            // 0..7  -> cols cg*4..cg*4+3

    for (int i = tid; i < NF * NH; i += 256) Ws[i] = W1[i];

    float acc[4][4];
#pragma unroll
    for (int i = 0; i < 4; i++)
#pragma unroll
        for (int j = 0; j < 4; j++) acc[i][j] = 0.f;

    for (int kc = 0; kc < 5; kc++) {
        __syncthreads();
#pragma unroll
        for (int j = 0; j < 10; j++) {
            int ii = tid + j * 256;          // 2560 elems: 128 rows x 20 k
            int r = ii / 20, kk = ii % 20;
            int gr = row0 + r;
            if (gr >= N_NODES) gr = N_NODES - 1;
            xs[kk * 132 + r] = x[(size_t)gr * NF + kc * 20 + kk];
        }
        __syncthreads();
#pragma unroll
        for (int kk = 0; kk < 20; kk++) {
            float4 xv = *(const float4*)&xs[kk * 132 + rg * 4];
            float4 wv = *(const float4*)&Ws[(kc * 20 + kk) * NH + cg * 4];
            acc[0][0] += xv.x * wv.x; acc[0][1] += xv.x * wv.y;
            acc[0][2] += xv.x * wv.z; acc[0][3] += xv.x * wv.w;
            acc[1][0] += xv.y * wv.x; acc[1][1] += xv.y * wv.y;
            acc[1][2] += xv.y * wv.z; acc[1][3] += xv.y * wv.w;
            acc[2][0] += xv.z * wv.x; acc[2][1] += xv.z * wv.y;
            acc[2][2] += xv.z * wv.z; acc[2][3] += xv.z * wv.w;
            acc[3][0] += xv.w * wv.x; acc[3][1] += xv.w * wv.y;
            acc[3][2] += xv.w * wv.z; acc[3][3] += xv.w * wv.w;
        }
    }

#pragma unroll
    for (int ri = 0; ri < 4; ri++) {
        int gr = row0 + rg * 4 + ri;
        if (gr < N_NODES) {
            float di = g_dinv[gr];
            float s2 = di * di;
            float4 hv = make_float4(acc[ri][0], acc[ri][1], acc[ri][2], acc[ri][3]);
            *(float4*)&g_h[(size_t)gr * NH + cg * 4] = hv;
            float4 ov = make_float4(hv.x * s2, hv.y * s2, hv.z * s2, hv.w * s2);
            *(float4*)&g_out1[(size_t)gr * NH + cg * 4] = ov;
        }
    }
}

// Layer-1 edge scatter: 4 lanes per edge, each handles 8 floats (2x float4).
__global__ __launch_bounds__(256) void k_edge1(const void* ei) {
    long long t = (long long)blockIdx.x * 256 + threadIdx.x;
    long long e = t >> 2;
    int sub = (int)(t & 3);
    if (e >= N_EDGES) return;
    int is64 = g_is64;
    int s = ld_idx(ei, e, is64);
    int d = ld_idx(ei, (long long)N_EDGES + e, is64);
    float w = __ldg(&g_dinv[s]) * __ldg(&g_dinv[d]);
    const float4* hp = (const float4*)(g_h + (size_t)s * NH) + sub * 2;
    float4 a = __ldg(hp), b = __ldg(hp + 1);
    a.x *= w; a.y *= w; a.z *= w; a.w *= w;
    b.x *= w; b.y *= w; b.z *= w; b.w *= w;
    float* op = g_out1 + (size_t)d * NH + sub * 8;
    red_add_v4(op, a);
    red_add_v4(op + 4, b);
}

// Post: h2 = dropout(relu(out1+b1)); g = h2 @ W2; init d_out with self-loop term.
// One warp per node row (32 cols). Dropout bits: partitionable threefry.
__global__ __launch_bounds__(256) void k_post(const float* __restrict__ b1,
                                              const float* __restrict__ W2,
                                              float* __restrict__ out) {
    int t = blockIdx.x * 256 + threadIdx.x;
    int r = t >> 5;
    int c = t & 31;
    if (r >= N_NODES) return;

    unsigned idx = (unsigned)(r * 32 + c);           // flat element index
    unsigned bits = rng_bits_partitionable(idx);

    float b1c = __ldg(&b1[c]);
    float w20 = __ldg(&W2[c * 2 + 0]);
    float w21 = __ldg(&W2[c * 2 + 1]);

    float v = g_out1[(size_t)r * NH + c] + b1c;
    v = fmaxf(v, 0.f);
    v = ((bits >> 9) < 6710887u) ? v * 1.25f : 0.f;  // keep iff u < 0.8f

    float p0 = v * w20, p1 = v * w21;
#pragma unroll
    for (int off = 16; off; off >>= 1) {
        p0 += __shfl_xor_sync(0xffffffffu, p0, off);
        p1 += __shfl_xor_sync(0xffffffffu, p1, off);
    }
    if (c == 0) {
        float di = g_dinv[r];
        float s2 = di * di;
        g_g[r * 2 + 0] = p0;
        g_g[r * 2 + 1] = p1;
        out[r * 2 + 0] = p0 * s2;
        out[r * 2 + 1] = p1 * s2;
    }
}

// Layer-2 edge scatter: 1 thread per edge, 2 floats.
__global__ __launch_bounds__(256) void k_edge2(const void* ei, float* __restrict__ out) {
    int e = blockIdx.x * 256 + threadIdx.x;
    if (e >= N_EDGES) return;
    int is64 = g_is64;
    int s = ld_idx(ei, e, is64);
    int d = ld_idx(ei, (long long)N_EDGES + e, is64);
    float w = __ldg(&g_dinv[s]) * __ldg(&g_dinv[d]);
    float2 gv = *(const float2*)(g_g + (size_t)s * 2);
    red_add_v2(out + (size_t)d * 2, gv.x * w, gv.y * w);
}

// Add b2 and in-place 2-class log_softmax.
__global__ __launch_bounds__(256) void k_final(const float* __restrict__ b2,
                                               float* __restrict__ out) {
    int i = blockIdx.x * 256 + threadIdx.x;
    if (i >= N_NODES) return;
    float2 l = ((float2*)out)[i];
    float a = l.x + __ldg(&b2[0]);
    float b = l.y + __ldg(&b2[1]);
    float m = fmaxf(a, b);
    float lse = m + logf(expf(a - m) + expf(b - m));
    ((float2*)out)[i] = make_float2(a - lse, b - lse);
}

// ---------------- launch ----------------
extern "C" void kernel_launch(void* const* d_in, const int* in_sizes, int n_in,
                              void* d_out, int out_size) {
    const float* x  = (const float*)d_in[0];
    const void*  ei = d_in[1];
    const float* W1 = (const float*)d_in[2];
    const float* b1 = (const float*)d_in[3];
    const float* W2 = (const float*)d_in[4];
    const float* b2 = (const float*)d_in[5];
    float* out = (float*)d_out;

    k_detect<<<1, 256>>>((const unsigned*)ei);
    k_deg_init<<<(N_NODES + 255) / 256, 256>>>();
    k_deg_count<<<(N_EDGES + 255) / 256, 256>>>(ei);
    k_dinv<<<(N_NODES + 255) / 256, 256>>>();
    k_gemm1<<<(N_NODES + 127) / 128, 256>>>(x, W1);
    k_edge1<<<(int)(((long long)N_EDGES * 4 + 255) / 256), 256>>>(ei);
    k_post<<<(int)(((long long)N_NODES * 32 + 255) / 256), 256>>>(b1, W2, out);
    k_edge2<<<(N_EDGES + 255) / 256, 256>>>(ei, out);
    k_final<<<(N_NODES + 255) / 256, 256>>>(b2, out);
}